// round 6
// baseline (speedup 1.0000x reference)
#include <cuda_runtime.h>
#include <math.h>

#define N_NODES 100000
#define N_EDGES 1600000
#define F_IN 50
#define FP 52               // padded feature count (16B-aligned rows)
#define NC 32
#define NEG_INF __int_as_float(0xFF800000)

// ---- Scratch (device globals — no allocation allowed) ----
__device__ int   g_csr_src[N_EDGES];
__device__ int   g_deg[N_NODES];
__device__ int   g_rowptr[N_NODES];
__device__ int   g_cursor[N_NODES];
__device__ int   g_excl[N_NODES];
__device__ int   g_bsums[256];
__device__ int   g_is64;
__device__ float g_xpad[N_NODES * FP];
__device__ float g_h1[N_NODES * NC];
__device__ float g_h2[N_NODES * NC];

// ---- Edge dtype detection: one warp, ballot ----
__global__ void detect_dtype_kernel(const int* __restrict__ ei_raw) {
    int lane = threadIdx.x;
    int nz = (ei_raw[2 * lane + 1] != 0) | (ei_raw[2 * (lane + 32) + 1] != 0);
    unsigned any = __ballot_sync(0xffffffff, nz);
    if (lane == 0) g_is64 = (any == 0u);
}

__global__ void zero_deg_kernel(int* __restrict__ deg) {
    int i = blockIdx.x * blockDim.x + threadIdx.x;
    if (i < N_NODES) deg[i] = 0;
}

__global__ void pad_x_kernel(const float* __restrict__ x, float* __restrict__ xpad) {
    int i = blockIdx.x * blockDim.x + threadIdx.x;
    if (i >= N_NODES * FP) return;
    int r = i / FP, c = i - r * FP;
    xpad[i] = (c < F_IN) ? x[r * F_IN + c] : 0.0f;
}

__global__ void histogram_kernel(const void* __restrict__ ei_raw, int* __restrict__ deg) {
    int i = blockIdx.x * blockDim.x + threadIdx.x;
    if (i >= N_EDGES) return;
    int d;
    if (g_is64) d = (int)((const long long*)ei_raw)[N_EDGES + i];
    else        d = ((const int*)ei_raw)[N_EDGES + i];
    atomicAdd(&deg[d], 1);
}

#define SCAN_BS 512
__global__ void scan_partial_kernel(const int* __restrict__ deg,
                                    int* __restrict__ excl, int* __restrict__ bsums) {
    __shared__ int s[SCAN_BS];
    int i = blockIdx.x * SCAN_BS + threadIdx.x;
    int v = (i < N_NODES) ? deg[i] : 0;
    s[threadIdx.x] = v;
    __syncthreads();
    for (int off = 1; off < SCAN_BS; off <<= 1) {
        int t = (threadIdx.x >= off) ? s[threadIdx.x - off] : 0;
        __syncthreads();
        s[threadIdx.x] += t;
        __syncthreads();
    }
    if (i < N_NODES) excl[i] = s[threadIdx.x] - v;
    if (threadIdx.x == SCAN_BS - 1) bsums[blockIdx.x] = s[SCAN_BS - 1];
}

__global__ void scan_bsums_kernel(int* __restrict__ bsums, int nb) {
    __shared__ int s[256];
    int t = threadIdx.x;
    s[t] = (t < nb) ? bsums[t] : 0;
    __syncthreads();
    if (t == 0) {
        int acc = 0;
        for (int i = 0; i < nb; i++) { int v = s[i]; s[i] = acc; acc += v; }
    }
    __syncthreads();
    if (t < nb) bsums[t] = s[t];
}

__global__ void scan_finish_kernel(const int* __restrict__ excl, const int* __restrict__ bsums,
                                   int* __restrict__ rowptr, int* __restrict__ cursor) {
    int i = blockIdx.x * blockDim.x + threadIdx.x;
    if (i >= N_NODES) return;
    int v = excl[i] + bsums[i / SCAN_BS];
    rowptr[i] = v;
    cursor[i] = v;
}

__global__ void bucket_scatter_kernel(const void* __restrict__ ei_raw,
                                      int* __restrict__ cursor, int* __restrict__ csr_src) {
    int i = blockIdx.x * blockDim.x + threadIdx.x;
    if (i >= N_EDGES) return;
    int s, d;
    if (g_is64) {
        const long long* p = (const long long*)ei_raw;
        s = (int)p[i];
        d = (int)p[N_EDGES + i];
    } else {
        const int* p = (const int*)ei_raw;
        s = p[i];
        d = p[N_EDGES + i];
    }
    int pos = atomicAdd(&cursor[d], 1);
    csr_src[pos] = s;
}

__device__ __forceinline__ float4 f4max(float4 a, float4 b) {
    return make_float4(fmaxf(a.x, b.x), fmaxf(a.y, b.y), fmaxf(a.z, b.z), fmaxf(a.w, b.w));
}

// ---- Layer 1 fused: float4 gather-max on padded x + linear + ReLU. 4 nodes/block. ----
__global__ void __launch_bounds__(256)
sage_layer1_kernel(const float* __restrict__ xpad, const float* __restrict__ x,
                   const int* __restrict__ rowptr, const int* __restrict__ deg,
                   const int* __restrict__ csr_src,
                   const float* __restrict__ Wl, const float* __restrict__ bl,
                   const float* __restrict__ Wr,
                   float* __restrict__ out) {
    __shared__ float sWl[F_IN][NC];
    __shared__ float sWr[F_IN][NC];
    __shared__ float s_red[4][2][FP];   // [node slot][warp-in-pair][feature]
    __shared__ float s_part[8][NC];
    int tid = threadIdx.x;
    for (int i = tid; i < F_IN * NC; i += 256) {
        sWl[i / NC][i % NC] = Wl[i];
        sWr[i / NC][i % NC] = Wr[i];
    }

    // Phase 1: 64 threads per node = 4 neighbor slots x 16 threads (13 active, float4 each)
    int slot = tid >> 6;          // node slot 0..3
    int sub = tid & 63;
    int g = sub >> 4;             // neighbor group 0..3 (0,1 in warp0; 2,3 in warp1)
    int t = sub & 15;             // feature quarter 0..15 (t<13 active)
    int node = blockIdx.x * 4 + slot;
    int start = rowptr[node];
    int d = deg[node];

    float4 vm = make_float4(NEG_INF, NEG_INF, NEG_INF, NEG_INF);
    if (t < 13) {
        int j = 0;
        for (; j + 16 <= d; j += 16) {
            int s0 = csr_src[start + j + g];
            int s1 = csr_src[start + j + 4 + g];
            int s2 = csr_src[start + j + 8 + g];
            int s3 = csr_src[start + j + 12 + g];
            float4 a0 = *(const float4*)&xpad[s0 * FP + 4 * t];
            float4 a1 = *(const float4*)&xpad[s1 * FP + 4 * t];
            float4 a2 = *(const float4*)&xpad[s2 * FP + 4 * t];
            float4 a3 = *(const float4*)&xpad[s3 * FP + 4 * t];
            vm = f4max(vm, f4max(f4max(a0, a1), f4max(a2, a3)));
        }
        for (; j < d; j += 4) {
            int n = j + g;
            if (n < d) {
                int s0 = csr_src[start + n];
                vm = f4max(vm, *(const float4*)&xpad[s0 * FP + 4 * t]);
            }
        }
    }
    // reduce groups within warp (g pairs differ by lane 16)
    vm.x = fmaxf(vm.x, __shfl_xor_sync(0xffffffff, vm.x, 16));
    vm.y = fmaxf(vm.y, __shfl_xor_sync(0xffffffff, vm.y, 16));
    vm.z = fmaxf(vm.z, __shfl_xor_sync(0xffffffff, vm.z, 16));
    vm.w = fmaxf(vm.w, __shfl_xor_sync(0xffffffff, vm.w, 16));
    int wp = (sub >> 5);          // warp in pair
    if (t < 13 && g == (wp << 1)) {   // one writer per (slot, wp, t)
        s_red[slot][wp][4 * t + 0] = vm.x;
        s_red[slot][wp][4 * t + 1] = vm.y;
        s_red[slot][wp][4 * t + 2] = vm.z;
        s_red[slot][wp][4 * t + 3] = vm.w;
    }
    __syncthreads();

    // Phase 2: linear. warp w: node w/2, k-half w&1, lane = col
    int w = tid >> 5;
    int c = tid & 31;
    int nl = w >> 1;
    int r = blockIdx.x * 4 + nl;
    int dr = deg[r];
    int kbeg = (w & 1) * 25;
    const float* xr = x + r * F_IN;
    float acc = (w & 1) ? 0.0f : bl[c];
#pragma unroll
    for (int k0 = 0; k0 < 25; k0++) {
        int k = kbeg + k0;
        float a = fmaxf(s_red[nl][0][k], s_red[nl][1][k]);
        if (dr == 0) a = 0.0f;
        acc += a * sWl[k][c] + xr[k] * sWr[k][c];
    }
    s_part[w][c] = acc;
    __syncthreads();

    if (w < 4) {
        int rr = blockIdx.x * 4 + w;
        float v = s_part[2 * w][c] + s_part[2 * w + 1][c];
        out[rr * NC + c] = fmaxf(v, 0.0f);
    }
}

// ---- Layers 2/3 fused: warp per node, float4 gather (4 slots x 8 threads) + shuffle-GEMV ----
template <bool RELU, bool LSM>
__global__ void __launch_bounds__(256)
sage_layer_f32_kernel(const float* __restrict__ hin,
                      const int* __restrict__ rowptr, const int* __restrict__ deg,
                      const int* __restrict__ csr_src,
                      const float* __restrict__ Wl, const float* __restrict__ bl,
                      const float* __restrict__ Wr,
                      float* __restrict__ out) {
    __shared__ float sWl[NC][NC];
    __shared__ float sWr[NC][NC];
    int tid = threadIdx.x;
    for (int i = tid; i < NC * NC; i += 256) {
        sWl[i / NC][i % NC] = Wl[i];
        sWr[i / NC][i % NC] = Wr[i];
    }

    int w = tid >> 5;
    int lane = tid & 31;
    int g = lane >> 3;        // neighbor slot 0..3
    int t = lane & 7;         // feature quarter 0..7
    int node = blockIdx.x * 8 + w;

    float bias = bl[lane];
    int start = rowptr[node];
    int d = deg[node];
    float4 xv4 = *(const float4*)&hin[node * NC + 4 * t];

    float4 vm = make_float4(NEG_INF, NEG_INF, NEG_INF, NEG_INF);
    int j = 0;
    for (; j + 16 <= d; j += 16) {
        int s0 = csr_src[start + j + g];
        int s1 = csr_src[start + j + 4 + g];
        int s2 = csr_src[start + j + 8 + g];
        int s3 = csr_src[start + j + 12 + g];
        float4 a0 = *(const float4*)&hin[s0 * NC + 4 * t];
        float4 a1 = *(const float4*)&hin[s1 * NC + 4 * t];
        float4 a2 = *(const float4*)&hin[s2 * NC + 4 * t];
        float4 a3 = *(const float4*)&hin[s3 * NC + 4 * t];
        vm = f4max(vm, f4max(f4max(a0, a1), f4max(a2, a3)));
    }
    for (; j < d; j += 4) {
        int n = j + g;
        if (n < d) {
            int s0 = csr_src[start + n];
            vm = f4max(vm, *(const float4*)&hin[s0 * NC + 4 * t]);
        }
    }
    // reduce across the 4 neighbor slots (lanes differ by 8 and 16)
#pragma unroll
    for (int off = 8; off <= 16; off <<= 1) {
        vm.x = fmaxf(vm.x, __shfl_xor_sync(0xffffffff, vm.x, off));
        vm.y = fmaxf(vm.y, __shfl_xor_sync(0xffffffff, vm.y, off));
        vm.z = fmaxf(vm.z, __shfl_xor_sync(0xffffffff, vm.z, off));
        vm.w = fmaxf(vm.w, __shfl_xor_sync(0xffffffff, vm.w, off));
    }
    float vr[4], xr4[4];
    if (d == 0) { vm.x = vm.y = vm.z = vm.w = 0.0f; }
    vr[0] = vm.x; vr[1] = vm.y; vr[2] = vm.z; vr[3] = vm.w;
    xr4[0] = xv4.x; xr4[1] = xv4.y; xr4[2] = xv4.z; xr4[3] = xv4.w;

    __syncthreads();   // weights ready

    // GEMV: acc_c = sum_k v_k*Wl[k][c] + x_k*Wr[k][c]; v_k held by lane k>>2 in vr[k&3]
    float acc = bias;
#pragma unroll
    for (int k = 0; k < NC; k++) {
        float vk = __shfl_sync(0xffffffff, vr[k & 3], k >> 2);
        float xk = __shfl_sync(0xffffffff, xr4[k & 3], k >> 2);
        acc += vk * sWl[k][lane] + xk * sWr[k][lane];
    }

    if (RELU) acc = fmaxf(acc, 0.0f);
    if (LSM) {
        float m = acc;
#pragma unroll
        for (int o = 16; o; o >>= 1) m = fmaxf(m, __shfl_xor_sync(0xffffffff, m, o));
        float ex = __expf(acc - m);
        float s = ex;
#pragma unroll
        for (int o = 16; o; o >>= 1) s += __shfl_xor_sync(0xffffffff, s, o);
        acc = acc - m - __logf(s);
    }
    out[node * NC + lane] = acc;
}

extern "C" void kernel_launch(void* const* d_in, const int* in_sizes, int n_in,
                              void* d_out, int out_size) {
    const float* x = (const float*)d_in[0];
    const void* ei = d_in[1];
    const float* Wl1 = (const float*)d_in[2];
    const float* bl1 = (const float*)d_in[3];
    const float* Wr1 = (const float*)d_in[4];
    const float* Wl2 = (const float*)d_in[5];
    const float* bl2 = (const float*)d_in[6];
    const float* Wr2 = (const float*)d_in[7];
    const float* Wl3 = (const float*)d_in[8];
    const float* bl3 = (const float*)d_in[9];
    const float* Wr3 = (const float*)d_in[10];
    float* out = (float*)d_out;

    float *xpad, *h1, *h2;
    int *csr_src, *deg, *rowptr, *cursor, *excl, *bsums;
    cudaGetSymbolAddress((void**)&xpad, g_xpad);
    cudaGetSymbolAddress((void**)&h1, g_h1);
    cudaGetSymbolAddress((void**)&h2, g_h2);
    cudaGetSymbolAddress((void**)&csr_src, g_csr_src);
    cudaGetSymbolAddress((void**)&deg, g_deg);
    cudaGetSymbolAddress((void**)&rowptr, g_rowptr);
    cudaGetSymbolAddress((void**)&cursor, g_cursor);
    cudaGetSymbolAddress((void**)&excl, g_excl);
    cudaGetSymbolAddress((void**)&bsums, g_bsums);

    const int eb = (N_EDGES + 255) / 256;
    const int nb = (N_NODES + 255) / 256;
    const int scan_blocks = (N_NODES + SCAN_BS - 1) / SCAN_BS;

    // ---- CSR build + x padding ----
    detect_dtype_kernel<<<1, 32>>>((const int*)ei);
    zero_deg_kernel<<<nb, 256>>>(deg);
    pad_x_kernel<<<(N_NODES * FP + 255) / 256, 256>>>(x, xpad);
    histogram_kernel<<<eb, 256>>>(ei, deg);
    scan_partial_kernel<<<scan_blocks, SCAN_BS>>>(deg, excl, bsums);
    scan_bsums_kernel<<<1, 256>>>(bsums, scan_blocks);
    scan_finish_kernel<<<nb, 256>>>(excl, bsums, rowptr, cursor);
    bucket_scatter_kernel<<<eb, 256>>>(ei, cursor, csr_src);

    // ---- Fused layers ----
    sage_layer1_kernel<<<N_NODES / 4, 256>>>(xpad, x, rowptr, deg, csr_src, Wl1, bl1, Wr1, h1);
    sage_layer_f32_kernel<true, false><<<N_NODES / 8, 256>>>(h1, rowptr, deg, csr_src,
                                                             Wl2, bl2, Wr2, h2);
    sage_layer_f32_kernel<false, true><<<N_NODES / 8, 256>>>(h2, rowptr, deg, csr_src,
                                                             Wl3, bl3, Wr3, out);
}